// round 3
// baseline (speedup 1.0000x reference)
#include <cuda_runtime.h>
#include <math.h>

#define T_STEPS 51
#define BATCH   1024
#define SDIM    27
#define HDIM    128
#define EDIM    770
#define DDIM    131
#define ROWS    8
#define NCTA    128
#define NTHR    256
#define STRIDE  904

typedef unsigned long long ull;

__device__ float g_w1t [898*512];
__device__ float g_wlt [7*256*512];
__device__ float g_bias[8*512];
__device__ float g_attnT[128*131];
__device__ float g_d1t [259*512];
__device__ float g_d2t [512*256];
__device__ float g_d3t [256*256];
__device__ float g_d4t [256*256];
__device__ float g_d5t [256*64];

__device__ __forceinline__ void fma2(ull& d, ull a, ull b) {
    asm("fma.rn.f32x2 %0, %1, %2, %0;" : "+l"(d) : "l"(a), "l"(b));
}
__device__ __forceinline__ ull add2(ull a, ull b) {
    ull r; asm("add.rn.f32x2 %0, %1, %2;" : "=l"(r) : "l"(a), "l"(b)); return r;
}
__device__ __forceinline__ ull pack2(float x) {
    ull r; int xi = __float_as_int(x);
    asm("mov.b64 %0, {%1, %1};" : "=l"(r) : "r"(xi));
    return r;
}
__device__ __forceinline__ float sigf(float x){ return 1.f/(1.f+expf(-x)); }

__global__ void prep_kernel(const float* __restrict__ w_ih1,
                            const float* __restrict__ w_ihr,
                            const float* __restrict__ w_hh,
                            const float* __restrict__ b_ih,
                            const float* __restrict__ b_hh,
                            const float* __restrict__ attn_w,
                            const float* __restrict__ d1_w,
                            const float* __restrict__ d2_w,
                            const float* __restrict__ d3_w,
                            const float* __restrict__ d4_w,
                            const float* __restrict__ d5_w)
{
    int g = blockIdx.x*blockDim.x + threadIdx.x;
    int st = gridDim.x*blockDim.x;
    for (int i=g; i<898*512; i+=st){
        int k=i>>9, j=i&511;
        g_w1t[i] = (k<770) ? w_ih1[j*770+k] : w_hh[j*128 + (k-770)];
    }
    for (int i=g; i<7*256*512; i+=st){
        int l = i/(256*512); int rem = i - l*256*512;
        int k = rem>>9, j = rem&511;
        g_wlt[i] = (k<128) ? w_ihr[(l*512+j)*128 + k]
                           : w_hh [((l+1)*512+j)*128 + (k-128)];
    }
    for (int i=g; i<8*512;  i+=st) g_bias[i] = b_ih[i] + b_hh[i];
    for (int i=g; i<128*131;i+=st){ int k=i/131, j=i-k*131; g_attnT[i]=attn_w[j*128+k]; }
    for (int i=g; i<259*512;i+=st){ int k=i>>9, j=i&511; g_d1t[i]=d1_w[j*259+k]; }
    for (int i=g; i<512*256;i+=st){ int k=i>>8, j=i&255; g_d2t[i]=d2_w[j*512+k]; }
    for (int i=g; i<256*256;i+=st){ int k=i>>8, j=i&255; g_d3t[i]=d3_w[j*256+k];
                                    g_d4t[i]=d4_w[j*256+k]; }
    for (int i=g; i<256*64; i+=st){ int k=i>>6, j=i&63;  g_d5t[i]=(j<51)? d5_w[j*256+k] : 0.f; }
}

// 8 rows x NOUT GEMM tile. 256 thr: kg=tid>>7 (k-half), rg=(tid>>6)&1 (4 rows), gg=tid&63.
template<int GT>
__device__ __forceinline__ void gemm_tile(const float* __restrict__ W,
                                          const float* __restrict__ bias,
                                          const float* src, float* dst,
                                          int K, int NOUT, int tid)
{
    const int kg = tid >> 7;
    const int rg = (tid >> 6) & 1;
    const int gg = tid & 63;
    const int j0 = gg * GT;
    const int r0 = rg * 4;
    const int kmid = K >> 1;
    const int kb = kg ? kmid : 0;
    const int ke = kg ? K    : kmid;
    constexpr int NP = GT/2;

    ull acc[4][NP];
    #pragma unroll
    for (int r=0;r<4;r++)
        #pragma unroll
        for (int p=0;p<NP;p++) acc[r][p] = 0ull;

    const float* Wp = W + (size_t)kb*NOUT + j0;
    const float* x0 = src + r0*STRIDE;

    #pragma unroll 4
    for (int k=kb; k<ke; k++, Wp+=NOUT) {
        ull w[NP];
        #pragma unroll
        for (int q=0; q<NP/2; q++){
            ulonglong2 ww = *(const ulonglong2*)(Wp + 4*q);
            w[2*q] = ww.x; w[2*q+1] = ww.y;
        }
        #pragma unroll
        for (int r=0;r<4;r++){
            ull xx = pack2(x0[r*STRIDE + k]);
            #pragma unroll
            for (int p=0;p<NP;p++) fma2(acc[r][p], w[p], xx);
        }
    }

    if (kg == 0) {
        #pragma unroll
        for (int r=0;r<4;r++)
            #pragma unroll
            for (int p=0;p<NP;p++) {
                ull b = *(const ull*)(bias + j0 + 2*p);
                *(ull*)(dst + (r0+r)*STRIDE + j0 + 2*p) = add2(acc[r][p], b);
            }
    }
    __syncthreads();
    if (kg == 1) {
        #pragma unroll
        for (int r=0;r<4;r++)
            #pragma unroll
            for (int p=0;p<NP;p++) {
                ull* a = (ull*)(dst + (r0+r)*STRIDE + j0 + 2*p);
                *a = add2(*a, acc[r][p]);
            }
    }
    __syncthreads();
}

template<int N>
__device__ __forceinline__ void relu_buf(float* buf, int tid){
    for (int i=tid; i<ROWS*N; i+=NTHR){
        int r = i / N, j = i - r*N;
        float v = buf[r*STRIDE + j];
        buf[r*STRIDE + j] = v > 0.f ? v : 0.f;
    }
    __syncthreads();
}

__global__ void __launch_bounds__(NTHR, 1)
eyet_kernel(const float* __restrict__ dec_emb, const float* __restrict__ enc_out,
            const int*   __restrict__ sp_pos,  const float* __restrict__ attn_b,
            const float* __restrict__ d1_b, const float* __restrict__ d2_b,
            const float* __restrict__ d3_b, const float* __restrict__ d4_b,
            const float* __restrict__ d5_b,
            float* __restrict__ out_loc, float* __restrict__ out_att)
{
    extern __shared__ float sm[];
    float* bufA = sm;                    // [8][STRIDE]
    float* bufB = sm + 8*STRIDE;         // [8][STRIDE]
    float* sh_h = sm + 16*STRIDE;        // [8 layers][8 rows][128]
    float* sh_c = sh_h + 8192;
    float* sh_q = sh_c + 8192;           // [8][132]

    const int tid = threadIdx.x;
    const int rowbase = blockIdx.x * ROWS;

    for (int i=tid; i<16384; i+=NTHR) sh_h[i] = 0.f;   // zeros h and c
    __syncthreads();

    for (int t=0; t<T_STEPS; t++) {
        // layer-0 input [x(770) | h0_prev(128)]
        for (int r=0;r<ROWS;r++){
            const float* xg = dec_emb + ((size_t)t*BATCH + rowbase + r)*EDIM;
            for (int k=tid; k<EDIM; k+=NTHR) bufA[r*STRIDE + k] = xg[k];
        }
        for (int i=tid; i<ROWS*HDIM; i+=NTHR){
            int r = i>>7, k = i&127;
            bufA[r*STRIDE + EDIM + k] = sh_h[(0*8 + r)*HDIM + k];
        }
        __syncthreads();

        for (int l=0; l<8; l++){
            if (l == 0){
                gemm_tile<8>(g_w1t, g_bias, bufA, bufB, 898, 512, tid);
            } else {
                for (int i=tid; i<ROWS*HDIM; i+=NTHR){
                    int r = i>>7, k = i&127;
                    bufA[r*STRIDE + k]        = sh_h[((l-1)*8 + r)*HDIM + k];
                    bufA[r*STRIDE + HDIM + k] = sh_h[(l*8 + r)*HDIM + k];
                }
                __syncthreads();
                gemm_tile<8>(g_wlt + (size_t)(l-1)*256*512, g_bias + l*512,
                             bufA, bufB, 256, 512, tid);
            }
            {   // i,f,g,o -> h,c
                int u = tid & 127, hh = tid >> 7;
                #pragma unroll
                for (int rr=0; rr<4; rr++){
                    int r = hh*4 + rr;
                    float gi = bufB[r*STRIDE + u];
                    float gf = bufB[r*STRIDE + 128 + u];
                    float gc = bufB[r*STRIDE + 256 + u];
                    float go = bufB[r*STRIDE + 384 + u];
                    int idx = (l*8 + r)*HDIM + u;
                    float c = sigf(gf)*sh_c[idx] + sigf(gi)*tanhf(gc);
                    sh_c[idx] = c;
                    sh_h[idx] = sigf(go)*tanhf(c);
                }
            }
            __syncthreads();
        }

        // q = ht @ attnT + b
        if (tid < DDIM){
            float acc[8];
            #pragma unroll
            for (int r=0;r<8;r++) acc[r] = 0.f;
            for (int k=0;k<HDIM;k++){
                float w = g_attnT[k*DDIM + tid];
                #pragma unroll
                for (int r=0;r<8;r++) acc[r] += w * sh_h[(56+r)*HDIM + k];
            }
            float bb = attn_b[tid];
            #pragma unroll
            for (int r=0;r<8;r++) sh_q[r*132 + tid] = acc[r] + bb;
        }
        __syncthreads();

        // windowed attention: one warp per row
        {
            int r = tid >> 5, lane = tid & 31;
            int b = rowbase + r;
            int pos   = sp_pos[b*T_STEPS + t];
            int left  = max(pos-1, 0);
            int right = min(pos+1, SDIM-1);
            int s1i = min(left+1, SDIM-1);
            int s2i = min(left+2, SDIM-1);
            const float* e0p = enc_out + ((size_t)b*SDIM + left)*DDIM;
            const float* e1p = enc_out + ((size_t)b*SDIM + s1i)*DDIM;
            const float* e2p = enc_out + ((size_t)b*SDIM + s2i)*DDIM;
            const float* qv  = sh_q + r*132;

            float s0=0.f, s1=0.f, s2=0.f;
            for (int d=lane; d<DDIM; d+=32){
                float qd = qv[d];
                s0 += qd*e0p[d]; s1 += qd*e1p[d]; s2 += qd*e2p[d];
            }
            #pragma unroll
            for (int off=16; off; off>>=1){
                s0 += __shfl_xor_sync(0xffffffffu, s0, off);
                s1 += __shfl_xor_sync(0xffffffffu, s1, off);
                s2 += __shfl_xor_sync(0xffffffffu, s2, off);
            }
            int wsz = right - left;                 // 1 or 2
            float m = fmaxf(s0, s1); if (wsz >= 2) m = fmaxf(m, s2);
            float ex0 = expf(s0 - m);
            float ex1 = expf(s1 - m);
            float ex2 = (wsz >= 2) ? expf(s2 - m) : 0.f;
            float inv = 1.f/(ex0 + ex1 + ex2);
            const float GA = 0.13533528323661270f;  // exp(-2)
            float a0 = ex0*inv * ((left   == pos) ? 1.f : GA);
            float a1 = ex1*inv * ((left+1 == pos) ? 1.f : GA);
            float a2 = ex2*inv * GA;

            for (int d=lane; d<DDIM; d+=32)
                bufA[r*STRIDE + d] = a0*e0p[d] + a1*e1p[d] + a2*e2p[d];
            for (int u=lane; u<HDIM; u+=32)
                bufA[r*STRIDE + DDIM + u] = sh_h[(56+r)*HDIM + u];

            if (lane < SDIM){
                float v = 0.f;
                if (lane >= left && lane <= right){
                    int i = lane - left;
                    v = (i==0)? a0 : (i==1)? a1 : a2;
                }
                out_att[((size_t)b*T_STEPS + t)*SDIM + lane] = v;
            }
        }
        __syncthreads();

        // dense head
        gemm_tile<8>(g_d1t, d1_b, bufA, bufB, 259, 512, tid);
        relu_buf<512>(bufB, tid);
        gemm_tile<4>(g_d2t, d2_b, bufB, bufA, 512, 256, tid);
        relu_buf<256>(bufA, tid);
        gemm_tile<4>(g_d3t, d3_b, bufA, bufB, 256, 256, tid);
        relu_buf<256>(bufB, tid);
        gemm_tile<4>(g_d4t, d4_b, bufB, bufA, 256, 256, tid);
        relu_buf<256>(bufA, tid);

        {   // d5: [8 rows] x 51
            int j = tid & 63, rq = tid >> 6;
            if (j < 51){
                int ra = rq*2, rb = rq*2+1;
                float a0=0.f, a1=0.f;
                for (int k=0;k<256;k++){
                    float w = g_d5t[k*64 + j];
                    a0 += w * bufA[ra*STRIDE + k];
                    a1 += w * bufA[rb*STRIDE + k];
                }
                float bb = d5_b[j];
                out_loc[((size_t)(rowbase+ra)*T_STEPS + t)*51 + j] = a0 + bb;
                out_loc[((size_t)(rowbase+rb)*T_STEPS + t)*51 + j] = a1 + bb;
            }
        }
        __syncthreads();
    }
}

static const int SMEM_BYTES = (16*STRIDE + 2*8192 + 8*132) * (int)sizeof(float);

extern "C" void kernel_launch(void* const* d_in, const int* in_sizes, int n_in,
                              void* d_out, int out_size)
{
    (void)in_sizes; (void)n_in; (void)out_size;
    const float* dec    = (const float*)d_in[0];
    const float* enc    = (const float*)d_in[1];
    const int*   sp     = (const int*)  d_in[3];
    const float* w_ih1  = (const float*)d_in[4];
    const float* w_ihr  = (const float*)d_in[5];
    const float* w_hh   = (const float*)d_in[6];
    const float* b_ih   = (const float*)d_in[7];
    const float* b_hh   = (const float*)d_in[8];
    const float* attn_w = (const float*)d_in[9];
    const float* attn_b = (const float*)d_in[10];
    const float* d1w=(const float*)d_in[11]; const float* d1b=(const float*)d_in[12];
    const float* d2w=(const float*)d_in[13]; const float* d2b=(const float*)d_in[14];
    const float* d3w=(const float*)d_in[15]; const float* d3b=(const float*)d_in[16];
    const float* d4w=(const float*)d_in[17]; const float* d4b=(const float*)d_in[18];
    const float* d5w=(const float*)d_in[19]; const float* d5b=(const float*)d_in[20];

    float* out_loc = (float*)d_out;
    float* out_att = out_loc + (size_t)BATCH*T_STEPS*51;

    cudaFuncSetAttribute(eyet_kernel, cudaFuncAttributeMaxDynamicSharedMemorySize, SMEM_BYTES);

    prep_kernel<<<256, 256>>>(w_ih1, w_ihr, w_hh, b_ih, b_hh, attn_w,
                              d1w, d2w, d3w, d4w, d5w);
    eyet_kernel<<<NCTA, NTHR, SMEM_BYTES>>>(dec, enc, sp, attn_b,
                                            d1b, d2b, d3b, d4b, d5b,
                                            out_loc, out_att);
}

// round 5
// speedup vs baseline: 1.2064x; 1.2064x over previous
#include <cuda_runtime.h>
#include <math.h>

#define T_STEPS 51
#define BATCH   1024
#define SDIM    27
#define HDIM    128
#define EDIM    770
#define DDIM    131
#define ROWS    8
#define NCTA    128
#define NTHR    512
#define STRIDE  904

typedef unsigned long long ull;

// pair-packed weights: W2[(kp*NOUT + j)*2 + s] = W[j][2*kp+s]
__device__ __align__(16) float g_w1t[449*512*2];
__device__ __align__(16) float g_wlt[7*128*512*2];
__device__ __align__(16) float g_bias[8*512];
__device__ __align__(16) float g_attnT[128*131];
__device__ __align__(16) float g_d1t[130*512*2];
__device__ __align__(16) float g_d2t[256*256*2];
__device__ __align__(16) float g_d3t[128*256*2];
__device__ __align__(16) float g_d4t[128*256*2];
__device__ __align__(16) float g_d5t[256*64];

__device__ __forceinline__ void fma2(ull& d, ull a, ull b) {
    asm("fma.rn.f32x2 %0, %1, %2, %0;" : "+l"(d) : "l"(a), "l"(b));
}
__device__ __forceinline__ float unpack_sum(ull a){
    float lo, hi;
    asm("mov.b64 {%0,%1}, %2;" : "=f"(lo), "=f"(hi) : "l"(a));
    return lo + hi;
}
__device__ __forceinline__ float sigf(float x){ return 1.f/(1.f+expf(-x)); }

__global__ void prep_kernel(const float* __restrict__ w_ih1,
                            const float* __restrict__ w_ihr,
                            const float* __restrict__ w_hh,
                            const float* __restrict__ b_ih,
                            const float* __restrict__ b_hh,
                            const float* __restrict__ attn_w,
                            const float* __restrict__ d1_w,
                            const float* __restrict__ d2_w,
                            const float* __restrict__ d3_w,
                            const float* __restrict__ d4_w,
                            const float* __restrict__ d5_w)
{
    int g = blockIdx.x*blockDim.x + threadIdx.x;
    int st = gridDim.x*blockDim.x;
    for (int i=g; i<449*1024; i+=st){
        int kp=i>>10, rem=i&1023, j=rem>>1, s=rem&1, k=2*kp+s;
        g_w1t[i] = (k<770) ? w_ih1[j*770+k] : w_hh[j*128 + (k-770)];
    }
    for (int i=g; i<7*128*1024; i+=st){
        int l=i/(128*1024); int rem=i-l*(128*1024);
        int kp=rem>>10, r2=rem&1023, j=r2>>1, s=r2&1, k=2*kp+s;
        g_wlt[i] = (k<128) ? w_ihr[(l*512+j)*128+k]
                           : w_hh [((l+1)*512+j)*128+(k-128)];
    }
    for (int i=g; i<8*512;  i+=st) g_bias[i] = b_ih[i] + b_hh[i];
    for (int i=g; i<128*131;i+=st){ int k=i/131, j=i-k*131; g_attnT[i]=attn_w[j*128+k]; }
    for (int i=g; i<130*1024; i+=st){
        int kp=i>>10, r2=i&1023, j=r2>>1, s=r2&1, k=2*kp+s;
        g_d1t[i] = (k<259) ? d1_w[j*259+k] : 0.f;
    }
    for (int i=g; i<256*512; i+=st){
        int kp=i>>9, r2=i&511, j=r2>>1, s=r2&1, k=2*kp+s;
        g_d2t[i] = d2_w[j*512+k];
    }
    for (int i=g; i<128*512; i+=st){
        int kp=i>>9, r2=i&511, j=r2>>1, s=r2&1, k=2*kp+s;
        g_d3t[i] = d3_w[j*256+k];
        g_d4t[i] = d4_w[j*256+k];
    }
    for (int i=g; i<256*64; i+=st){ int k=i>>6, j=i&63; g_d5t[i]=(j<51)? d5_w[j*256+k] : 0.f; }
}

// pair-k GEMM: 8 rows x NOUT. 512 thr: kg = tid/(NOUT/2) k-slabs, gg j-pairs.
// Partials (even+odd k merged) -> sP[(kg*8+r)*512 + j].
template<int NOUT>
__device__ __forceinline__ void gemm2(const float* __restrict__ W2,
                                      const float* src, int srcStride,
                                      int Kpairs, float* sP, int tid)
{
    constexpr int KG = 1024/NOUT;          // 2 (NOUT=512) or 4 (NOUT=256)
    const int kg = tid / (NOUT/2);
    const int gg = tid - kg*(NOUT/2);
    const int j0 = gg*2;
    const int kb = (Kpairs*kg)/KG;
    const int ke = (Kpairs*(kg+1))/KG;

    ull a0[8], a1[8];
    #pragma unroll
    for (int r=0;r<8;r++){ a0[r]=0ull; a1[r]=0ull; }

    const float* wp = W2 + (size_t)kb*(NOUT*2) + j0*2;
    #pragma unroll 2
    for (int kp=kb; kp<ke; kp++, wp += NOUT*2){
        ulonglong2 ww = *(const ulonglong2*)wp;
        const float* s0 = src + 2*kp;
        #pragma unroll
        for (int r=0;r<8;r++){
            ull xx = *(const ull*)(s0 + r*srcStride);
            fma2(a0[r], ww.x, xx);
            fma2(a1[r], ww.y, xx);
        }
    }
    float* pr = sP + (kg*8)*512 + j0;
    #pragma unroll
    for (int r=0;r<8;r++){
        pr[r*512 + 0] = unpack_sum(a0[r]);
        pr[r*512 + 1] = unpack_sum(a1[r]);
    }
}

// combine 2 k-slabs + bias, LSTM gate math, update h/c (sh layout [r][l][128])
__device__ __forceinline__ void lstm_combine(const float* sP, const float* __restrict__ bias,
                                             float* sh_h, float* sh_c, int l, int tid)
{
    #pragma unroll
    for (int it=0; it<2; it++){
        int i = tid + it*NTHR;
        int r = i>>7, u = i&127;
        const float* p0 = sP + r*512;
        const float* p1 = sP + (8+r)*512;
        float gi = p0[u]     + p1[u]     + bias[u];
        float gf = p0[u+128] + p1[u+128] + bias[u+128];
        float gc = p0[u+256] + p1[u+256] + bias[u+256];
        float go = p0[u+384] + p1[u+384] + bias[u+384];
        int idx = r*1024 + l*128 + u;
        float c = sigf(gf)*sh_c[idx] + sigf(gi)*tanhf(gc);
        sh_c[idx] = c;
        sh_h[idx] = sigf(go)*tanhf(c);
    }
}

__device__ __forceinline__ void comb2_relu(const float* sP, const float* __restrict__ bias,
                                           float* dst, int dstStride, int tid)
{
    #pragma unroll
    for (int it=0; it<8; it++){
        int i = tid + it*NTHR;
        int r = i>>9, j = i&511;
        float v = sP[r*512+j] + sP[(8+r)*512+j] + bias[j];
        dst[r*dstStride + j] = v>0.f ? v : 0.f;
    }
}
__device__ __forceinline__ void comb4_relu(const float* sP, const float* __restrict__ bias,
                                           float* dst, int dstStride, int tid)
{
    #pragma unroll
    for (int it=0; it<4; it++){
        int i = tid + it*NTHR;
        int r = i>>8, j = i&255;
        float v = sP[r*512+j] + sP[(8+r)*512+j] + sP[(16+r)*512+j] + sP[(24+r)*512+j] + bias[j];
        dst[r*dstStride + j] = v>0.f ? v : 0.f;
    }
}

__global__ void __launch_bounds__(NTHR, 1)
eyet_kernel(const float* __restrict__ dec_emb, const float* __restrict__ enc_out,
            const int*   __restrict__ sp_pos,  const float* __restrict__ attn_b,
            const float* __restrict__ d1_b, const float* __restrict__ d2_b,
            const float* __restrict__ d3_b, const float* __restrict__ d4_b,
            const float* __restrict__ d5_b,
            float* __restrict__ out_loc, float* __restrict__ out_att)
{
    extern __shared__ float sm[];
    float* bufA = sm;                       // [8][904]   layer0 input / feat
    float* sP   = sm + 7232;                // [32][512]  GEMM partials
    float* sh_h = sm + 7232 + 16384;        // [8 rows][8 layers][128]
    float* sh_c = sh_h + 8192;
    float* sh_q = sh_c + 8192;              // [8][132]
    float* bufD = sh_q + 1056;              // [8][512]
    float* bufE = bufD + 4096;              // [8][256]

    const int tid = threadIdx.x;
    const int rowbase = blockIdx.x * ROWS;

    for (int i=tid; i<16384; i+=NTHR) sh_h[i] = 0.f;   // h and c contiguous
    __syncthreads();

    for (int t=0; t<T_STEPS; t++) {
        // stage layer-0 input [x(770) | h0(128)]
        for (int r=0;r<ROWS;r++){
            const float* xg = dec_emb + ((size_t)t*BATCH + rowbase + r)*EDIM;
            for (int k=tid; k<EDIM; k+=NTHR) bufA[r*STRIDE + k] = xg[k];
        }
        for (int i=tid; i<ROWS*HDIM; i+=NTHR){
            int r = i>>7, u = i&127;
            bufA[r*STRIDE + EDIM + u] = sh_h[r*1024 + u];
        }
        __syncthreads();

        gemm2<512>(g_w1t, bufA, STRIDE, 449, sP, tid);
        __syncthreads();
        lstm_combine(sP, g_bias, sh_h, sh_c, 0, tid);
        __syncthreads();
        for (int l=1; l<8; l++){
            gemm2<512>(g_wlt + (size_t)(l-1)*(128*1024), sh_h + (l-1)*128, 1024, 128, sP, tid);
            __syncthreads();
            lstm_combine(sP, g_bias + l*512, sh_h, sh_c, l, tid);
            __syncthreads();
        }

        // q = ht @ attnT + b   (ht = sh_h[r][7][:])
        if (tid < 262){
            int half = tid >= 131 ? 1 : 0;
            int j = tid - half*131;
            int rb = half*4;
            float acc[4] = {0.f,0.f,0.f,0.f};
            for (int k=0;k<HDIM;k++){
                float w = g_attnT[k*DDIM + j];
                #pragma unroll
                for (int q=0;q<4;q++) acc[q] += w * sh_h[(rb+q)*1024 + 896 + k];
            }
            float bb = attn_b[j];
            #pragma unroll
            for (int q=0;q<4;q++) sh_q[(rb+q)*132 + j] = acc[q] + bb;
        }
        __syncthreads();

        // windowed attention: one warp per row (warps 0-7)
        if (tid < 256){
            int r = tid >> 5, lane = tid & 31;
            int b = rowbase + r;
            int pos   = sp_pos[b*T_STEPS + t];
            int left  = max(pos-1, 0);
            int right = min(pos+1, SDIM-1);
            int s1i = min(left+1, SDIM-1);
            int s2i = min(left+2, SDIM-1);
            const float* e0p = enc_out + ((size_t)b*SDIM + left)*DDIM;
            const float* e1p = enc_out + ((size_t)b*SDIM + s1i)*DDIM;
            const float* e2p = enc_out + ((size_t)b*SDIM + s2i)*DDIM;
            const float* qv  = sh_q + r*132;

            float s0=0.f, s1=0.f, s2=0.f;
            for (int d=lane; d<DDIM; d+=32){
                float qd = qv[d];
                s0 += qd*e0p[d]; s1 += qd*e1p[d]; s2 += qd*e2p[d];
            }
            #pragma unroll
            for (int off=16; off; off>>=1){
                s0 += __shfl_xor_sync(0xffffffffu, s0, off);
                s1 += __shfl_xor_sync(0xffffffffu, s1, off);
                s2 += __shfl_xor_sync(0xffffffffu, s2, off);
            }
            int wsz = right - left;
            float m = fmaxf(s0, s1); if (wsz >= 2) m = fmaxf(m, s2);
            float ex0 = expf(s0 - m);
            float ex1 = expf(s1 - m);
            float ex2 = (wsz >= 2) ? expf(s2 - m) : 0.f;
            float inv = 1.f/(ex0 + ex1 + ex2);
            const float GA = 0.13533528323661270f;   // exp(-2)
            float a0 = ex0*inv * ((left   == pos) ? 1.f : GA);
            float a1 = ex1*inv * ((left+1 == pos) ? 1.f : GA);
            float a2 = ex2*inv * GA;

            for (int d=lane; d<DDIM; d+=32)
                bufA[r*STRIDE + d] = a0*e0p[d] + a1*e1p[d] + a2*e2p[d];
            for (int u=lane; u<HDIM; u+=32)
                bufA[r*STRIDE + DDIM + u] = sh_h[r*1024 + 896 + u];
            if (lane == 0) bufA[r*STRIDE + 259] = 0.f;   // pad for k-pair (K 259->260)

            if (lane < SDIM){
                float v = 0.f;
                if (lane >= left && lane <= right){
                    int i = lane - left;
                    v = (i==0)? a0 : (i==1)? a1 : a2;
                }
                out_att[((size_t)b*T_STEPS + t)*SDIM + lane] = v;
            }
        }
        __syncthreads();

        // dense head
        gemm2<512>(g_d1t, bufA, STRIDE, 130, sP, tid);
        __syncthreads();
        comb2_relu(sP, d1_b, bufD, 512, tid);
        __syncthreads();
        gemm2<256>(g_d2t, bufD, 512, 256, sP, tid);
        __syncthreads();
        comb4_relu(sP, d2_b, bufE, 256, tid);
        __syncthreads();
        gemm2<256>(g_d3t, bufE, 256, 128, sP, tid);
        __syncthreads();
        comb4_relu(sP, d3_b, bufD, 256, tid);
        __syncthreads();
        gemm2<256>(g_d4t, bufD, 256, 128, sP, tid);
        __syncthreads();
        comb4_relu(sP, d4_b, bufE, 256, tid);
        __syncthreads();

        {   // d5: 8 rows x 51, one thread per (r,j)
            int j = tid & 63, r = tid >> 6;
            if (j < 51){
                float a = 0.f;
                const float* xr = bufE + r*256;
                for (int k=0;k<256;k++) a += g_d5t[k*64 + j] * xr[k];
                out_loc[((size_t)(rowbase+r)*T_STEPS + t)*51 + j] = a + d5_b[j];
            }
        }
        __syncthreads();
    }
}

static const int SMEM_BYTES = (7232 + 16384 + 8192 + 8192 + 1056 + 4096 + 2048) * (int)sizeof(float);

extern "C" void kernel_launch(void* const* d_in, const int* in_sizes, int n_in,
                              void* d_out, int out_size)
{
    (void)in_sizes; (void)n_in; (void)out_size;
    const float* dec    = (const float*)d_in[0];
    const float* enc    = (const float*)d_in[1];
    const int*   sp     = (const int*)  d_in[3];
    const float* w_ih1  = (const float*)d_in[4];
    const float* w_ihr  = (const float*)d_in[5];
    const float* w_hh   = (const float*)d_in[6];
    const float* b_ih   = (const float*)d_in[7];
    const float* b_hh   = (const float*)d_in[8];
    const float* attn_w = (const float*)d_in[9];
    const float* attn_b = (const float*)d_in[10];
    const float* d1w=(const float*)d_in[11]; const float* d1b=(const float*)d_in[12];
    const float* d2w=(const float*)d_in[13]; const float* d2b=(const float*)d_in[14];
    const float* d3w=(const float*)d_in[15]; const float* d3b=(const float*)d_in[16];
    const float* d4w=(const float*)d_in[17]; const float* d4b=(const float*)d_in[18];
    const float* d5w=(const float*)d_in[19]; const float* d5b=(const float*)d_in[20];

    float* out_loc = (float*)d_out;
    float* out_att = out_loc + (size_t)BATCH*T_STEPS*51;

    cudaFuncSetAttribute(eyet_kernel, cudaFuncAttributeMaxDynamicSharedMemorySize, SMEM_BYTES);

    prep_kernel<<<256, 256>>>(w_ih1, w_ihr, w_hh, b_ih, b_hh, attn_w,
                              d1w, d2w, d3w, d4w, d5w);
    eyet_kernel<<<NCTA, NTHR, SMEM_BYTES>>>(dec, enc, sp, attn_b,
                                            d1b, d2b, d3b, d4b, d5b,
                                            out_loc, out_att);
}

// round 11
// speedup vs baseline: 1.3025x; 1.0796x over previous
#include <cuda_runtime.h>
#include <math.h>

#define T_STEPS 51
#define BATCH   1024
#define SDIM    27
#define HDIM    128
#define EDIM    770
#define DDIM    131
#define ROWS    8
#define NCTA    128
#define NTHR    512
#define STRIDE  904

typedef unsigned long long ull;

// pair-packed weights: W2[(kp*NOUT + j)*2 + s] = W[j][2*kp+s]
__device__ __align__(16) float g_w1t[452*512*2];      // K padded 898->904
__device__ __align__(16) float g_wlt[7*128*512*2];
__device__ __align__(16) float g_bias[8*512];
__device__ __align__(16) float g_attnT[128*131];
__device__ __align__(16) float g_d1t[132*512*2];      // K padded 259->264
__device__ __align__(16) float g_d2t[256*256*2];
__device__ __align__(16) float g_d3t[128*256*2];
__device__ __align__(16) float g_d4t[128*256*2];
__device__ __align__(16) float g_d5t[256*64];

__device__ __forceinline__ void fma2(ull& d, ull a, ull b) {
    asm("fma.rn.f32x2 %0, %1, %2, %0;" : "+l"(d) : "l"(a), "l"(b));
}
__device__ __forceinline__ float unpack_sum(ull a){
    float lo, hi;
    asm("mov.b64 {%0,%1}, %2;" : "=f"(lo), "=f"(hi) : "l"(a));
    return lo + hi;
}
// fast sigmoid: correct limits at +-inf (exp(-x)->inf => 0, ->0 => 1)
__device__ __forceinline__ float sig_fast(float x){
    return __fdividef(1.f, 1.f + __expf(-x));
}
// fast tanh via e^(-2|x|) in (0,1]: no overflow, exact at 0, rel err ~1e-7
__device__ __forceinline__ float tanh_fast(float x){
    float t = __expf(-2.f*fabsf(x));
    float y = __fdividef(1.f - t, 1.f + t);
    return copysignf(y, x);
}

__global__ void prep_kernel(const float* __restrict__ w_ih1,
                            const float* __restrict__ w_ihr,
                            const float* __restrict__ w_hh,
                            const float* __restrict__ b_ih,
                            const float* __restrict__ b_hh,
                            const float* __restrict__ attn_w,
                            const float* __restrict__ d1_w,
                            const float* __restrict__ d2_w,
                            const float* __restrict__ d3_w,
                            const float* __restrict__ d4_w,
                            const float* __restrict__ d5_w)
{
    int g = blockIdx.x*blockDim.x + threadIdx.x;
    int st = gridDim.x*blockDim.x;
    for (int i=g; i<452*1024; i+=st){
        int kp=i>>10, rem=i&1023, j=rem>>1, s=rem&1, k=2*kp+s;
        g_w1t[i] = (k<770) ? w_ih1[j*770+k] :
                   (k<898) ? w_hh[j*128 + (k-770)] : 0.f;
    }
    for (int i=g; i<7*128*1024; i+=st){
        int l=i/(128*1024); int rem=i-l*(128*1024);
        int kp=rem>>10, r2=rem&1023, j=r2>>1, s=r2&1, k=2*kp+s;
        g_wlt[i] = (k<128) ? w_ihr[(l*512+j)*128+k]
                           : w_hh [((l+1)*512+j)*128+(k-128)];
    }
    for (int i=g; i<8*512;  i+=st) g_bias[i] = b_ih[i] + b_hh[i];
    for (int i=g; i<128*131;i+=st){ int k=i/131, j=i-k*131; g_attnT[i]=attn_w[j*128+k]; }
    for (int i=g; i<132*1024; i+=st){
        int kp=i>>10, r2=i&1023, j=r2>>1, s=r2&1, k=2*kp+s;
        g_d1t[i] = (k<259) ? d1_w[j*259+k] : 0.f;
    }
    for (int i=g; i<256*512; i+=st){
        int kp=i>>9, r2=i&511, j=r2>>1, s=r2&1, k=2*kp+s;
        g_d2t[i] = d2_w[j*512+k];
    }
    for (int i=g; i<128*512; i+=st){
        int kp=i>>9, r2=i&511, j=r2>>1, s=r2&1, k=2*kp+s;
        g_d3t[i] = d3_w[j*256+k];
        g_d4t[i] = d4_w[j*256+k];
    }
    for (int i=g; i<256*64; i+=st){ int k=i>>6, j=i&63; g_d5t[i]=(j<51)? d5_w[j*256+k] : 0.f; }
}

// pair-k GEMM, 2 k-pairs per iter (LDS.128 x loads). 8 rows x NOUT.
// KG=1024/NOUT slabs; slab bounds are even kp for all instantiations.
template<int NOUT, int SSTR, int KPAIRS>
__device__ __forceinline__ void gemm2(const float* __restrict__ W2,
                                      const float* src, float* sP, int tid)
{
    constexpr int KG = 1024/NOUT;
    const int kg = tid / (NOUT/2);
    const int gg = tid - kg*(NOUT/2);
    const int j0 = gg*2;
    const int kb = (KPAIRS*kg)/KG;
    const int ke = (KPAIRS*(kg+1))/KG;

    ull a0[8], a1[8];
    #pragma unroll
    for (int r=0;r<8;r++){ a0[r]=0ull; a1[r]=0ull; }

    const float* wp = W2 + (size_t)(kb*NOUT + j0)*2;
    #pragma unroll 2
    for (int kp=kb; kp<ke; kp+=2, wp += NOUT*4){
        ulonglong2 w0 = *(const ulonglong2*)wp;
        ulonglong2 w1 = *(const ulonglong2*)(wp + NOUT*2);
        const float* s0 = src + 2*kp;
        #pragma unroll
        for (int r=0;r<8;r++){
            ulonglong2 xx = *(const ulonglong2*)(s0 + r*SSTR);
            fma2(a0[r], w0.x, xx.x);
            fma2(a1[r], w0.y, xx.x);
            fma2(a0[r], w1.x, xx.y);
            fma2(a1[r], w1.y, xx.y);
        }
    }
    float* pr = sP + (kg*8)*512 + j0;
    #pragma unroll
    for (int r=0;r<8;r++){
        float2 v = make_float2(unpack_sum(a0[r]), unpack_sum(a1[r]));
        *(float2*)(pr + r*512) = v;
    }
}

// combine 2 k-slabs + bias, LSTM gate math, update h/c (sh layout [r][l][128])
__device__ __forceinline__ void lstm_combine(const float* sP, const float* __restrict__ bias,
                                             float* sh_h, float* sh_c, int l, int tid)
{
    #pragma unroll
    for (int it=0; it<2; it++){
        int i = tid + it*NTHR;
        int r = i>>7, u = i&127;
        const float* p0 = sP + r*512;
        const float* p1 = sP + (8+r)*512;
        float gi = p0[u]     + p1[u]     + bias[u];
        float gf = p0[u+128] + p1[u+128] + bias[u+128];
        float gc = p0[u+256] + p1[u+256] + bias[u+256];
        float go = p0[u+384] + p1[u+384] + bias[u+384];
        int idx = r*1024 + l*128 + u;
        float c = sig_fast(gf)*sh_c[idx] + sig_fast(gi)*tanh_fast(gc);
        sh_c[idx] = c;
        sh_h[idx] = sig_fast(go)*tanh_fast(c);
    }
}

__device__ __forceinline__ void comb2_relu(const float* sP, const float* __restrict__ bias,
                                           float* dst, int dstStride, int tid)
{
    #pragma unroll
    for (int it=0; it<8; it++){
        int i = tid + it*NTHR;
        int r = i>>9, j = i&511;
        float v = sP[r*512+j] + sP[(8+r)*512+j] + bias[j];
        dst[r*dstStride + j] = v>0.f ? v : 0.f;
    }
}
__device__ __forceinline__ void comb4_relu(const float* sP, const float* __restrict__ bias,
                                           float* dst, int dstStride, int tid)
{
    #pragma unroll
    for (int it=0; it<4; it++){
        int i = tid + it*NTHR;
        int r = i>>8, j = i&255;
        float v = sP[r*512+j] + sP[(8+r)*512+j] + sP[(16+r)*512+j] + sP[(24+r)*512+j] + bias[j];
        dst[r*dstStride + j] = v>0.f ? v : 0.f;
    }
}

__global__ void __launch_bounds__(NTHR, 1)
eyet_kernel(const float* __restrict__ dec_emb, const float* __restrict__ enc_out,
            const int*   __restrict__ sp_pos,  const float* __restrict__ attn_b,
            const float* __restrict__ d1_b, const float* __restrict__ d2_b,
            const float* __restrict__ d3_b, const float* __restrict__ d4_b,
            const float* __restrict__ d5_b,
            float* __restrict__ out_loc, float* __restrict__ out_att)
{
    extern __shared__ float sm[];
    float* bufA = sm;                       // [8][904]   layer0 input / feat
    float* sP   = sm + 7232;                // [32][512]  GEMM partials
    float* sh_h = sm + 7232 + 16384;        // [8 rows][8 layers][128]
    float* sh_c = sh_h + 8192;
    float* sh_q = sh_c + 8192;              // [8][132]
    float* bufD = sh_q + 1056;              // [8][512]
    float* bufE = bufD + 4096;              // [8][256]

    const int tid = threadIdx.x;
    const int rowbase = blockIdx.x * ROWS;

    for (int i=tid; i<16384; i+=NTHR) sh_h[i] = 0.f;   // h and c contiguous
    // zero bufA K-pad region (898..903 per row), never touched again
    if (tid < 48){
        int r = tid/6, u = tid - r*6;
        bufA[r*STRIDE + 898 + u] = 0.f;
    }
    __syncthreads();

    for (int t=0; t<T_STEPS; t++) {
        // stage layer-0 input [x(770) | h0(128) | pad(6)=0]
        for (int r=0;r<ROWS;r++){
            const float* xg = dec_emb + ((size_t)t*BATCH + rowbase + r)*EDIM;
            for (int k=tid; k<EDIM; k+=NTHR) bufA[r*STRIDE + k] = xg[k];
        }
        for (int i=tid; i<ROWS*HDIM; i+=NTHR){
            int r = i>>7, u = i&127;
            bufA[r*STRIDE + EDIM + u] = sh_h[r*1024 + u];
        }
        __syncthreads();

        gemm2<512, STRIDE, 452>(g_w1t, bufA, sP, tid);
        __syncthreads();
        lstm_combine(sP, g_bias, sh_h, sh_c, 0, tid);
        __syncthreads();
        for (int l=1; l<8; l++){
            gemm2<512, 1024, 128>(g_wlt + (size_t)(l-1)*(128*1024), sh_h + (l-1)*128, sP, tid);
            __syncthreads();
            lstm_combine(sP, g_bias + l*512, sh_h, sh_c, l, tid);
            __syncthreads();
        }

        // q = ht @ attnT + b   (ht = sh_h[r][7][:])
        if (tid < 262){
            int half = tid >= 131 ? 1 : 0;
            int j = tid - half*131;
            int rb = half*4;
            float acc[4] = {0.f,0.f,0.f,0.f};
            for (int k=0;k<HDIM;k++){
                float w = g_attnT[k*DDIM + j];
                #pragma unroll
                for (int q=0;q<4;q++) acc[q] += w * sh_h[(rb+q)*1024 + 896 + k];
            }
            float bb = attn_b[j];
            #pragma unroll
            for (int q=0;q<4;q++) sh_q[(rb+q)*132 + j] = acc[q] + bb;
        }
        __syncthreads();

        // windowed attention: one warp per row (warps 0-7)
        if (tid < 256){
            int r = tid >> 5, lane = tid & 31;
            int b = rowbase + r;
            int pos   = sp_pos[b*T_STEPS + t];
            int left  = max(pos-1, 0);
            int right = min(pos+1, SDIM-1);
            int s1i = min(left+1, SDIM-1);
            int s2i = min(left+2, SDIM-1);
            const float* e0p = enc_out + ((size_t)b*SDIM + left)*DDIM;
            const float* e1p = enc_out + ((size_t)b*SDIM + s1i)*DDIM;
            const float* e2p = enc_out + ((size_t)b*SDIM + s2i)*DDIM;
            const float* qv  = sh_q + r*132;

            float s0=0.f, s1=0.f, s2=0.f;
            for (int d=lane; d<DDIM; d+=32){
                float qd = qv[d];
                s0 += qd*e0p[d]; s1 += qd*e1p[d]; s2 += qd*e2p[d];
            }
            #pragma unroll
            for (int off=16; off; off>>=1){
                s0 += __shfl_xor_sync(0xffffffffu, s0, off);
                s1 += __shfl_xor_sync(0xffffffffu, s1, off);
                s2 += __shfl_xor_sync(0xffffffffu, s2, off);
            }
            int wsz = right - left;
            float m = fmaxf(s0, s1); if (wsz >= 2) m = fmaxf(m, s2);
            float ex0 = expf(s0 - m);
            float ex1 = expf(s1 - m);
            float ex2 = (wsz >= 2) ? expf(s2 - m) : 0.f;
            float inv = 1.f/(ex0 + ex1 + ex2);
            const float GA = 0.13533528323661270f;   // exp(-2)
            float a0 = ex0*inv * ((left   == pos) ? 1.f : GA);
            float a1 = ex1*inv * ((left+1 == pos) ? 1.f : GA);
            float a2 = ex2*inv * GA;

            for (int d=lane; d<DDIM; d+=32)
                bufA[r*STRIDE + d] = a0*e0p[d] + a1*e1p[d] + a2*e2p[d];
            for (int u=lane; u<HDIM; u+=32)
                bufA[r*STRIDE + DDIM + u] = sh_h[r*1024 + 896 + u];
            if (lane < 5) bufA[r*STRIDE + 259 + lane] = 0.f;   // pad K 259->264

            if (lane < SDIM){
                float v = 0.f;
                if (lane >= left && lane <= right){
                    int i = lane - left;
                    v = (i==0)? a0 : (i==1)? a1 : a2;
                }
                out_att[((size_t)b*T_STEPS + t)*SDIM + lane] = v;
            }
        }
        __syncthreads();

        // dense head
        gemm2<512, STRIDE, 132>(g_d1t, bufA, sP, tid);
        __syncthreads();
        comb2_relu(sP, d1_b, bufD, 512, tid);
        __syncthreads();
        gemm2<256, 512, 256>(g_d2t, bufD, sP, tid);
        __syncthreads();
        comb4_relu(sP, d2_b, bufE, 256, tid);
        __syncthreads();
        gemm2<256, 256, 128>(g_d3t, bufE, sP, tid);
        __syncthreads();
        comb4_relu(sP, d3_b, bufD, 256, tid);
        __syncthreads();
        gemm2<256, 256, 128>(g_d4t, bufD, sP, tid);
        __syncthreads();
        comb4_relu(sP, d4_b, bufE, 256, tid);
        __syncthreads();

        {   // d5: 8 rows x 51, one thread per (r,j)
            int j = tid & 63, r = tid >> 6;
            if (j < 51){
                float a = 0.f;
                const float* xr = bufE + r*256;
                for (int k=0;k<256;k++) a += g_d5t[k*64 + j] * xr[k];
                out_loc[((size_t)(rowbase+r)*T_STEPS + t)*51 + j] = a + d5_b[j];
            }
        }
        __syncthreads();
    }
}

static const int SMEM_BYTES = (7232 + 16384 + 8192 + 8192 + 1056 + 4096 + 2048) * (int)sizeof(float);

extern "C" void kernel_launch(void* const* d_in, const int* in_sizes, int n_in,
                              void* d_out, int out_size)
{
    (void)in_sizes; (void)n_in; (void)out_size;
    const float* dec    = (const float*)d_in[0];
    const float* enc    = (const float*)d_in[1];
    const int*   sp     = (const int*)  d_in[3];
    const float* w_ih1  = (const float*)d_in[4];
    const float* w_ihr  = (const float*)d_in[5];
    const float* w_hh   = (const float*)d_in[6];
    const float* b_ih   = (const float*)d_in[7];
    const float* b_hh   = (const float*)d_in[8];
    const float* attn_w = (const float*)d_in[9];
    const float* attn_b = (const float*)d_in[10];
    const float* d1w=(const float*)d_in[11]; const float* d1b=(const float*)d_in[12];
    const float* d2w=(const float*)d_in[13]; const float* d2b=(const float*)d_in[14];
    const float* d3w=(const float*)d_in[15]; const float* d3b=(const float*)d_in[16];
    const float* d4w=(const float*)d_in[17]; const float* d4b=(const float*)d_in[18];
    const float* d5w=(const float*)d_in[19]; const float* d5b=(const float*)d_in[20];

    float* out_loc = (float*)d_out;
    float* out_att = out_loc + (size_t)BATCH*T_STEPS*51;

    cudaFuncSetAttribute(eyet_kernel, cudaFuncAttributeMaxDynamicSharedMemorySize, SMEM_BYTES);

    prep_kernel<<<256, 256>>>(w_ih1, w_ihr, w_hh, b_ih, b_hh, attn_w,
                              d1w, d2w, d3w, d4w, d5w);
    eyet_kernel<<<NCTA, NTHR, SMEM_BYTES>>>(dec, enc, sp, attn_b,
                                            d1b, d2b, d3b, d4b, d5b,
                                            out_loc, out_att);
}

// round 12
// speedup vs baseline: 1.5508x; 1.1907x over previous
#include <cuda_runtime.h>
#include <math.h>

#define T_STEPS 51
#define BATCH   1024
#define SDIM    27
#define HDIM    128
#define EDIM    770
#define DDIM    131
#define ROWS    8
#define NCTA    128
#define NTHR    512
#define STRIDE  912

typedef unsigned long long ull;

// plane-packed weights, iteration unit = 4 k x 4 j per thread:
// idx = ((i2*4 + plane)*JG + gg)*4 + f ; j = gg*4 + (plane&1)*2 + f/2 ;
// k = i2*4 + (plane>>1)*2 + (f&1)
__device__ __align__(16) float g_w1t[228*4*128*4];   // K padded 898->912
__device__ __align__(16) float g_wlt[7*64*4*128*4];  // K=256
__device__ __align__(16) float g_bias[8*512];
__device__ __align__(16) float g_attnT[128*131];
__device__ __align__(16) float g_d1t[68*4*128*4];    // K padded 259->272
__device__ __align__(16) float g_d2t[128*4*64*4];    // K=512, NOUT=256
__device__ __align__(16) float g_d3t[64*4*64*4];
__device__ __align__(16) float g_d4t[64*4*64*4];
__device__ __align__(16) float g_d5t[256*64];

__device__ __forceinline__ void fma2(ull& d, ull a, ull b) {
    asm("fma.rn.f32x2 %0, %1, %2, %0;" : "+l"(d) : "l"(a), "l"(b));
}
__device__ __forceinline__ float unpack_sum(ull a){
    float lo, hi;
    asm("mov.b64 {%0,%1}, %2;" : "=f"(lo), "=f"(hi) : "l"(a));
    return lo + hi;
}
__device__ __forceinline__ float sig_fast(float x){
    return __fdividef(1.f, 1.f + __expf(-x));
}
__device__ __forceinline__ float tanh_fast(float x){
    float t = __expf(-2.f*fabsf(x));
    float y = __fdividef(1.f - t, 1.f + t);
    return copysignf(y, x);
}

__device__ __forceinline__ void plane_decode(int i, int JG, int& j, int& k){
    int f = i & 3; int chunk = i >> 2;
    int gg = chunk % JG; int rest = chunk / JG;
    int plane = rest & 3; int i2 = rest >> 2;
    j = gg*4 + ((plane & 1) << 1) + (f >> 1);
    k = i2*4 + ((plane >> 1) << 1) + (f & 1);
}

__global__ void prep_kernel(const float* __restrict__ w_ih1,
                            const float* __restrict__ w_ihr,
                            const float* __restrict__ w_hh,
                            const float* __restrict__ b_ih,
                            const float* __restrict__ b_hh,
                            const float* __restrict__ attn_w,
                            const float* __restrict__ d1_w,
                            const float* __restrict__ d2_w,
                            const float* __restrict__ d3_w,
                            const float* __restrict__ d4_w,
                            const float* __restrict__ d5_w)
{
    int g = blockIdx.x*blockDim.x + threadIdx.x;
    int st = gridDim.x*blockDim.x;
    int j, k;
    for (int i=g; i<228*4*128*4; i+=st){
        plane_decode(i, 128, j, k);
        g_w1t[i] = (k<770) ? w_ih1[j*770+k] :
                   (k<898) ? w_hh[j*128 + (k-770)] : 0.f;
    }
    for (int i=g; i<7*64*4*128*4; i+=st){
        int l = i / (64*4*128*4); int rem = i - l*(64*4*128*4);
        plane_decode(rem, 128, j, k);
        g_wlt[i] = (k<128) ? w_ihr[(l*512+j)*128+k]
                           : w_hh [((l+1)*512+j)*128+(k-128)];
    }
    for (int i=g; i<8*512;  i+=st) g_bias[i] = b_ih[i] + b_hh[i];
    for (int i=g; i<128*131;i+=st){ int kk=i/131, jj=i-kk*131; g_attnT[i]=attn_w[jj*128+kk]; }
    for (int i=g; i<68*4*128*4; i+=st){
        plane_decode(i, 128, j, k);
        g_d1t[i] = (k<259) ? d1_w[j*259+k] : 0.f;
    }
    for (int i=g; i<128*4*64*4; i+=st){
        plane_decode(i, 64, j, k);
        g_d2t[i] = d2_w[j*512+k];
    }
    for (int i=g; i<64*4*64*4; i+=st){
        plane_decode(i, 64, j, k);
        g_d3t[i] = d3_w[j*256+k];
        g_d4t[i] = d4_w[j*256+k];
    }
    for (int i=g; i<256*64; i+=st){ int kk=i>>6, jj=i&63; g_d5t[i]=(jj<51)? d5_w[jj*256+kk] : 0.f; }
}

// GT=4 plane-packed GEMM: 8 rows x NOUT, KSLABS k-slabs, 4 j per thread.
// sP[(kg*8 + r)*NOUT + j]
template<int NOUT, int SSTR, int I2TOT, int KSLABS>
__device__ __forceinline__ void gemm4(const float* __restrict__ W,
                                      const float* src, float* sP, int tid)
{
    constexpr int JG = NOUT/4;
    const int kg = tid / JG;
    const int gg = tid - kg*JG;
    const int j0 = gg*4;
    const int i2b = (I2TOT*kg)/KSLABS;
    const int i2e = (I2TOT*(kg+1))/KSLABS;

    ull a0[8], a1[8], a2[8], a3[8];
    #pragma unroll
    for (int r=0;r<8;r++){ a0[r]=0ull; a1[r]=0ull; a2[r]=0ull; a3[r]=0ull; }

    const float* wp = W + (size_t)i2b*(16*JG) + j0;
    for (int i2=i2b; i2<i2e; i2++, wp += 16*JG){
        ulonglong2 wA = *(const ulonglong2*)(wp);
        ulonglong2 wB = *(const ulonglong2*)(wp + 4*JG);
        ulonglong2 wC = *(const ulonglong2*)(wp + 8*JG);
        ulonglong2 wD = *(const ulonglong2*)(wp + 12*JG);
        const float* s0 = src + i2*4;
        #pragma unroll
        for (int r=0;r<8;r++){
            ulonglong2 xx = *(const ulonglong2*)(s0 + r*SSTR);
            fma2(a0[r], wA.x, xx.x);
            fma2(a1[r], wA.y, xx.x);
            fma2(a2[r], wB.x, xx.x);
            fma2(a3[r], wB.y, xx.x);
            fma2(a0[r], wC.x, xx.y);
            fma2(a1[r], wC.y, xx.y);
            fma2(a2[r], wD.x, xx.y);
            fma2(a3[r], wD.y, xx.y);
        }
    }
    float* pr = sP + (kg*8)*NOUT + j0;
    #pragma unroll
    for (int r=0;r<8;r++){
        float4 v = make_float4(unpack_sum(a0[r]), unpack_sum(a1[r]),
                               unpack_sum(a2[r]), unpack_sum(a3[r]));
        *(float4*)(pr + r*NOUT) = v;
    }
}

// combine 4 k-slabs (NOUT=512) + bias, LSTM gates, update h/c ([r][l][128])
__device__ __forceinline__ void lstm_combine(const float* sP, const float* __restrict__ bias,
                                             float* sh_h, float* sh_c, int l, int tid)
{
    #pragma unroll
    for (int it=0; it<2; it++){
        int i = tid + it*NTHR;
        int r = i>>7, u = i&127;
        const float* p0 = sP + r*512;
        const float* p1 = sP + (8+r)*512;
        const float* p2 = sP + (16+r)*512;
        const float* p3 = sP + (24+r)*512;
        float gi = p0[u]     + p1[u]     + p2[u]     + p3[u]     + bias[u];
        float gf = p0[u+128] + p1[u+128] + p2[u+128] + p3[u+128] + bias[u+128];
        float gc = p0[u+256] + p1[u+256] + p2[u+256] + p3[u+256] + bias[u+256];
        float go = p0[u+384] + p1[u+384] + p2[u+384] + p3[u+384] + bias[u+384];
        int idx = r*1024 + l*128 + u;
        float c = sig_fast(gf)*sh_c[idx] + sig_fast(gi)*tanh_fast(gc);
        sh_c[idx] = c;
        sh_h[idx] = sig_fast(go)*tanh_fast(c);
    }
}

// 4 slabs, NOUT=512, relu
__device__ __forceinline__ void comb4_relu512(const float* sP, const float* __restrict__ bias,
                                              float* dst, int tid)
{
    #pragma unroll
    for (int it=0; it<8; it++){
        int i = tid + it*NTHR;
        int r = i>>9, j = i&511;
        float v = sP[r*512+j] + sP[(8+r)*512+j] + sP[(16+r)*512+j] + sP[(24+r)*512+j] + bias[j];
        dst[r*512 + j] = v>0.f ? v : 0.f;
    }
}
// 8 slabs, NOUT=256, relu
__device__ __forceinline__ void comb8_relu256(const float* sP, const float* __restrict__ bias,
                                              float* dst, int tid)
{
    #pragma unroll
    for (int it=0; it<4; it++){
        int i = tid + it*NTHR;
        int r = i>>8, j = i&255;
        float v = bias[j];
        #pragma unroll
        for (int s=0;s<8;s++) v += sP[(s*8+r)*256 + j];
        dst[r*256 + j] = v>0.f ? v : 0.f;
    }
}

__global__ void __launch_bounds__(NTHR, 1)
eyet_kernel(const float* __restrict__ dec_emb, const float* __restrict__ enc_out,
            const int*   __restrict__ sp_pos,  const float* __restrict__ attn_b,
            const float* __restrict__ d1_b, const float* __restrict__ d2_b,
            const float* __restrict__ d3_b, const float* __restrict__ d4_b,
            const float* __restrict__ d5_b,
            float* __restrict__ out_loc, float* __restrict__ out_att)
{
    extern __shared__ float sm[];
    float* bufA = sm;                       // [8][912]   layer0 input / feat
    float* sP   = sm + 7296;                // [<=64 rows][<=512] GEMM partials (16384)
    float* sh_h = sm + 7296 + 16384;        // [8 rows][8 layers][128]
    float* sh_c = sh_h + 8192;
    float* sh_q = sh_c + 8192;              // [8][132]
    float* bufD = sh_q + 1056;              // [8][512]
    float* bufE = bufD + 4096;              // [8][256]

    const int tid = threadIdx.x;
    const int rowbase = blockIdx.x * ROWS;

    for (int i=tid; i<16384; i+=NTHR) sh_h[i] = 0.f;   // h and c contiguous
    // zero bufA K-pad region (898..911 per row)
    if (tid < 112){
        int r = tid/14, u = tid - r*14;
        bufA[r*STRIDE + 898 + u] = 0.f;
    }
    __syncthreads();

    for (int t=0; t<T_STEPS; t++) {
        // stage layer-0 input [x(770) | h0(128) | pad(14)=0]
        for (int r=0;r<ROWS;r++){
            const float* xg = dec_emb + ((size_t)t*BATCH + rowbase + r)*EDIM;
            for (int k=tid; k<EDIM; k+=NTHR) bufA[r*STRIDE + k] = xg[k];
        }
        for (int i=tid; i<ROWS*HDIM; i+=NTHR){
            int r = i>>7, u = i&127;
            bufA[r*STRIDE + EDIM + u] = sh_h[r*1024 + u];
        }
        __syncthreads();

        gemm4<512, STRIDE, 228, 4>(g_w1t, bufA, sP, tid);
        __syncthreads();
        lstm_combine(sP, g_bias, sh_h, sh_c, 0, tid);
        __syncthreads();
        for (int l=1; l<8; l++){
            gemm4<512, 1024, 64, 4>(g_wlt + (size_t)(l-1)*(64*4*128*4), sh_h + (l-1)*128, sP, tid);
            __syncthreads();
            lstm_combine(sP, g_bias + l*512, sh_h, sh_c, l, tid);
            __syncthreads();
        }

        // q = ht @ attnT + b   (ht = sh_h[r][7][:])
        if (tid < 262){
            int half = tid >= 131 ? 1 : 0;
            int j = tid - half*131;
            int rb = half*4;
            float acc[4] = {0.f,0.f,0.f,0.f};
            for (int k=0;k<HDIM;k++){
                float w = g_attnT[k*DDIM + j];
                #pragma unroll
                for (int q=0;q<4;q++) acc[q] += w * sh_h[(rb+q)*1024 + 896 + k];
            }
            float bb = attn_b[j];
            #pragma unroll
            for (int q=0;q<4;q++) sh_q[(rb+q)*132 + j] = acc[q] + bb;
        }
        __syncthreads();

        // windowed attention: one warp per row (warps 0-7)
        if (tid < 256){
            int r = tid >> 5, lane = tid & 31;
            int b = rowbase + r;
            int pos   = sp_pos[b*T_STEPS + t];
            int left  = max(pos-1, 0);
            int right = min(pos+1, SDIM-1);
            int s1i = min(left+1, SDIM-1);
            int s2i = min(left+2, SDIM-1);
            const float* e0p = enc_out + ((size_t)b*SDIM + left)*DDIM;
            const float* e1p = enc_out + ((size_t)b*SDIM + s1i)*DDIM;
            const float* e2p = enc_out + ((size_t)b*SDIM + s2i)*DDIM;
            const float* qv  = sh_q + r*132;

            float s0=0.f, s1=0.f, s2=0.f;
            for (int d=lane; d<DDIM; d+=32){
                float qd = qv[d];
                s0 += qd*e0p[d]; s1 += qd*e1p[d]; s2 += qd*e2p[d];
            }
            #pragma unroll
            for (int off=16; off; off>>=1){
                s0 += __shfl_xor_sync(0xffffffffu, s0, off);
                s1 += __shfl_xor_sync(0xffffffffu, s1, off);
                s2 += __shfl_xor_sync(0xffffffffu, s2, off);
            }
            int wsz = right - left;
            float m = fmaxf(s0, s1); if (wsz >= 2) m = fmaxf(m, s2);
            float ex0 = expf(s0 - m);
            float ex1 = expf(s1 - m);
            float ex2 = (wsz >= 2) ? expf(s2 - m) : 0.f;
            float inv = 1.f/(ex0 + ex1 + ex2);
            const float GA = 0.13533528323661270f;   // exp(-2)
            float a0 = ex0*inv * ((left   == pos) ? 1.f : GA);
            float a1 = ex1*inv * ((left+1 == pos) ? 1.f : GA);
            float a2 = ex2*inv * GA;

            for (int d=lane; d<DDIM; d+=32)
                bufA[r*STRIDE + d] = a0*e0p[d] + a1*e1p[d] + a2*e2p[d];
            for (int u=lane; u<HDIM; u+=32)
                bufA[r*STRIDE + DDIM + u] = sh_h[r*1024 + 896 + u];
            if (lane < 13) bufA[r*STRIDE + 259 + lane] = 0.f;   // pad K 259->272

            if (lane < SDIM){
                float v = 0.f;
                if (lane >= left && lane <= right){
                    int i = lane - left;
                    v = (i==0)? a0 : (i==1)? a1 : a2;
                }
                out_att[((size_t)b*T_STEPS + t)*SDIM + lane] = v;
            }
        }
        __syncthreads();

        // dense head
        gemm4<512, STRIDE, 68, 4>(g_d1t, bufA, sP, tid);
        __syncthreads();
        comb4_relu512(sP, d1_b, bufD, tid);
        __syncthreads();
        gemm4<256, 512, 128, 8>(g_d2t, bufD, sP, tid);
        __syncthreads();
        comb8_relu256(sP, d2_b, bufE, tid);
        __syncthreads();
        gemm4<256, 256, 64, 8>(g_d3t, bufE, sP, tid);
        __syncthreads();
        comb8_relu256(sP, d3_b, bufD, tid);     // bufD reused as [8][256]
        __syncthreads();
        gemm4<256, 256, 64, 8>(g_d4t, bufD, sP, tid);
        __syncthreads();
        comb8_relu256(sP, d4_b, bufE, tid);
        __syncthreads();

        {   // d5: 8 rows x 51, one thread per (r,j)
            int j = tid & 63, r = tid >> 6;
            if (j < 51){
                float a = 0.f;
                const float* xr = bufE + r*256;
                for (int k=0;k<256;k++) a += g_d5t[k*64 + j] * xr[k];
                out_loc[((size_t)(rowbase+r)*T_STEPS + t)*51 + j] = a + d5_b[j];
            }
        }
        __syncthreads();
    }
}

static const int SMEM_BYTES = (7296 + 16384 + 8192 + 8192 + 1056 + 4096 + 2048) * (int)sizeof(float);

extern "C" void kernel_launch(void* const* d_in, const int* in_sizes, int n_in,
                              void* d_out, int out_size)
{
    (void)in_sizes; (void)n_in; (void)out_size;
    const float* dec    = (const float*)d_in[0];
    const float* enc    = (const float*)d_in[1];
    const int*   sp     = (const int*)  d_in[3];
    const float* w_ih1  = (const float*)d_in[4];
    const float* w_ihr  = (const float*)d_in[5];
    const float* w_hh   = (const float*)d_in[6];
    const float* b_ih   = (const float*)d_in[7];
    const float* b_hh   = (const float*)d_in[8];
    const float* attn_w = (const float*)d_in[9];
    const float* attn_b = (const float*)d_in[10];
    const float* d1w=(const float*)d_in[11]; const float* d1b=(const float*)d_in[12];
    const float* d2w=(const float*)d_in[13]; const float* d2b=(const float*)d_in[14];
    const float* d3w=(const float*)d_in[15]; const float* d3b=(const float*)d_in[16];
    const float* d4w=(const float*)d_in[17]; const float* d4b=(const float*)d_in[18];
    const float* d5w=(const float*)d_in[19]; const float* d5b=(const float*)d_in[20];

    float* out_loc = (float*)d_out;
    float* out_att = out_loc + (size_t)BATCH*T_STEPS*51;

    cudaFuncSetAttribute(eyet_kernel, cudaFuncAttributeMaxDynamicSharedMemorySize, SMEM_BYTES);

    prep_kernel<<<256, 256>>>(w_ih1, w_ihr, w_hh, b_ih, b_hh, attn_w,
                              d1w, d2w, d3w, d4w, d5w);
    eyet_kernel<<<NCTA, NTHR, SMEM_BYTES>>>(dec, enc, sp, attn_b,
                                            d1b, d2b, d3b, d4b, d5b,
                                            out_loc, out_att);
}